// round 2
// baseline (speedup 1.0000x reference)
#include <cuda_runtime.h>

#define Bb 16
#define Tt 2048
#define Cc 1024
#define Hh 64
#define Mm (Bb*Tt)

// Scratch for Q, K, V projections (8 MB each) — __device__ globals per harness rules.
__device__ float g_q[Mm*Hh];
__device__ float g_k[Mm*Hh];
__device__ float g_v[Mm*Hh];

// ---------------------------------------------------------------------------
// Kernel 1: QKV projection.  out = X[M,C] @ W[C,H], blockIdx.y in {0,1,2}
// BM=128, BN=64(=H), BK=16, 256 threads, per-thread 8x4 micro-tile.
// ---------------------------------------------------------------------------
__global__ __launch_bounds__(256) void qkv_kernel(
    const float* __restrict__ x,
    const float* __restrict__ wq,
    const float* __restrict__ wk,
    const float* __restrict__ wv)
{
    constexpr int BM = 128;
    constexpr int BK = 16;
    __shared__ float Xs[BK][BM + 4];   // [k][m], padded: float4-aligned, low conflicts
    __shared__ float Ws[BK][Hh + 4];   // [k][n]

    const float* w   = (blockIdx.y == 0) ? wq : (blockIdx.y == 1 ? wk : wv);
    float*       outp= (blockIdx.y == 0) ? g_q : (blockIdx.y == 1 ? g_k : g_v);

    const int m0  = blockIdx.x * BM;
    const int tid = threadIdx.x;
    const int tx  = tid & 15;          // 0..15 -> 4 output cols
    const int ty  = tid >> 4;          // 0..15 -> 8 output rows

    float acc[8][4];
    #pragma unroll
    for (int i = 0; i < 8; i++)
        #pragma unroll
        for (int j = 0; j < 4; j++) acc[i][j] = 0.f;

    const int xk = tid & 15;           // k-lane for X loads
    const int xm = tid >> 4;           // base row for X loads

    for (int k0 = 0; k0 < Cc; k0 += BK) {
        // Load X chunk [BM x BK] (coalesced along k), store transposed.
        #pragma unroll
        for (int i = 0; i < 8; i++) {
            int m = xm + i * 16;
            Xs[xk][m] = x[(size_t)(m0 + m) * Cc + k0 + xk];
        }
        // Load W chunk [BK x H] (coalesced along n).
        #pragma unroll
        for (int i = 0; i < 4; i++) {
            int e  = tid + i * 256;
            int kk = e >> 6, n = e & 63;
            Ws[kk][n] = w[(size_t)(k0 + kk) * Hh + n];
        }
        __syncthreads();

        #pragma unroll
        for (int kk = 0; kk < BK; kk++) {
            float4 a0 = *(const float4*)&Xs[kk][ty * 8];
            float4 a1 = *(const float4*)&Xs[kk][ty * 8 + 4];
            float4 b  = *(const float4*)&Ws[kk][tx * 4];
            float a[8] = {a0.x, a0.y, a0.z, a0.w, a1.x, a1.y, a1.z, a1.w};
            float bb[4] = {b.x, b.y, b.z, b.w};
            #pragma unroll
            for (int i = 0; i < 8; i++)
                #pragma unroll
                for (int j = 0; j < 4; j++)
                    acc[i][j] = fmaf(a[i], bb[j], acc[i][j]);
        }
        __syncthreads();
    }

    #pragma unroll
    for (int i = 0; i < 8; i++) {
        float4 r = make_float4(acc[i][0], acc[i][1], acc[i][2], acc[i][3]);
        *(float4*)&outp[(size_t)(m0 + ty * 8 + i) * Hh + tx * 4] = r;
    }
}

// ---------------------------------------------------------------------------
// Kernel 2: causal flash attention.  64x64 tiles, online softmax.
// 256 threads, thread (ty,tx) owns rows ty*4..+3, cols tx*4..+3.
// Smem layouts chosen so all inner-loop reads are conflict-free LDS.128:
//   Qts[h][r], Kts[h][s]  (transposed), Vs[s][h], Pts[s][r]  — stride 68.
// ---------------------------------------------------------------------------
#define PAD 68

__global__ __launch_bounds__(256) void attn_kernel(float* __restrict__ out)
{
    extern __shared__ float sm[];
    float* Qts = sm;                 // 64*68
    float* Kts = sm + 64 * PAD;
    float* Vs  = sm + 2 * 64 * PAD;
    float* Pts = sm + 3 * 64 * PAD;

    const int b  = blockIdx.y;
    const int qb = (gridDim.x - 1) - blockIdx.x;   // heavy (large-qb) tiles first
    const int tid = threadIdx.x;
    const int tx = tid & 15, ty = tid >> 4;

    const float* qptr  = g_q + ((size_t)b * Tt + (size_t)qb * 64) * Hh;
    const float* kbase = g_k + (size_t)b * Tt * Hh;
    const float* vbase = g_v + (size_t)b * Tt * Hh;

    // Load Q tile transposed: Qts[h][r]
    #pragma unroll
    for (int i = 0; i < 16; i++) {
        int e = tid + i * 256;
        int r = e >> 6, h = e & 63;
        Qts[h * PAD + r] = qptr[e];
    }

    float m_i[4], l_i[4], O[4][4];
    #pragma unroll
    for (int i = 0; i < 4; i++) {
        m_i[i] = -1e30f; l_i[i] = 0.f;
        #pragma unroll
        for (int j = 0; j < 4; j++) O[i][j] = 0.f;
    }
    const float scale = 0.125f;   // 1/sqrt(64)

    for (int kb = 0; kb <= qb; kb++) {
        __syncthreads();   // previous PV done before overwriting K/V tiles
        const float* kp = kbase + (size_t)kb * 64 * Hh;
        const float* vp = vbase + (size_t)kb * 64 * Hh;
        #pragma unroll
        for (int i = 0; i < 16; i++) {
            int e = tid + i * 256;
            int r = e >> 6, h = e & 63;
            Kts[h * PAD + r] = kp[e];
            Vs[r * PAD + h]  = vp[e];
        }
        __syncthreads();

        // S = Q K^T  (4x4 per thread)
        float s[4][4];
        #pragma unroll
        for (int i = 0; i < 4; i++)
            #pragma unroll
            for (int j = 0; j < 4; j++) s[i][j] = 0.f;

        #pragma unroll 8
        for (int kk = 0; kk < 64; kk++) {
            float4 a = *(const float4*)&Qts[kk * PAD + ty * 4];
            float4 c = *(const float4*)&Kts[kk * PAD + tx * 4];
            float av[4] = {a.x, a.y, a.z, a.w};
            float cv[4] = {c.x, c.y, c.z, c.w};
            #pragma unroll
            for (int i = 0; i < 4; i++)
                #pragma unroll
                for (int j = 0; j < 4; j++)
                    s[i][j] = fmaf(av[i], cv[j], s[i][j]);
        }

        // scale + causal mask on the diagonal block
        #pragma unroll
        for (int i = 0; i < 4; i++)
            #pragma unroll
            for (int j = 0; j < 4; j++) {
                s[i][j] *= scale;
                if (kb == qb && (tx * 4 + j) > (ty * 4 + i)) s[i][j] = -1e30f;
            }

        // online softmax (rows owned by 16 lanes sharing ty; reduce over tx bits)
        float p[4][4];
        float alpha[4];
        #pragma unroll
        for (int i = 0; i < 4; i++) {
            float mr = fmaxf(fmaxf(s[i][0], s[i][1]), fmaxf(s[i][2], s[i][3]));
            #pragma unroll
            for (int off = 8; off >= 1; off >>= 1)
                mr = fmaxf(mr, __shfl_xor_sync(0xffffffffu, mr, off));
            float mn = fmaxf(m_i[i], mr);
            alpha[i] = __expf(m_i[i] - mn);
            float rs = 0.f;
            #pragma unroll
            for (int j = 0; j < 4; j++) {
                p[i][j] = __expf(s[i][j] - mn);
                rs += p[i][j];
            }
            #pragma unroll
            for (int off = 8; off >= 1; off >>= 1)
                rs += __shfl_xor_sync(0xffffffffu, rs, off);
            l_i[i] = l_i[i] * alpha[i] + rs;
            m_i[i] = mn;
            #pragma unroll
            for (int j = 0; j < 4; j++) O[i][j] *= alpha[i];
        }

        // stage P transposed: Pts[s][r]
        #pragma unroll
        for (int i = 0; i < 4; i++)
            #pragma unroll
            for (int j = 0; j < 4; j++)
                Pts[(tx * 4 + j) * PAD + ty * 4 + i] = p[i][j];
        __syncthreads();

        // O += P V
        #pragma unroll 8
        for (int ss = 0; ss < 64; ss++) {
            float4 a = *(const float4*)&Pts[ss * PAD + ty * 4];
            float4 c = *(const float4*)&Vs[ss * PAD + tx * 4];
            float av[4] = {a.x, a.y, a.z, a.w};
            float cv[4] = {c.x, c.y, c.z, c.w};
            #pragma unroll
            for (int i = 0; i < 4; i++)
                #pragma unroll
                for (int j = 0; j < 4; j++)
                    O[i][j] = fmaf(av[i], cv[j], O[i][j]);
        }
    }

    // epilogue: normalize and write
    #pragma unroll
    for (int i = 0; i < 4; i++) {
        float inv = 1.f / l_i[i];
        float4 r = make_float4(O[i][0] * inv, O[i][1] * inv, O[i][2] * inv, O[i][3] * inv);
        size_t row = (size_t)b * Tt + (size_t)qb * 64 + ty * 4 + i;
        *(float4*)&out[row * Hh + tx * 4] = r;
    }
}

// ---------------------------------------------------------------------------
extern "C" void kernel_launch(void* const* d_in, const int* in_sizes, int n_in,
                              void* d_out, int out_size)
{
    const float* x  = (const float*)d_in[0];
    const float* wq = (const float*)d_in[1];
    const float* wk = (const float*)d_in[2];
    const float* wv = (const float*)d_in[3];
    float* out = (float*)d_out;

    qkv_kernel<<<dim3(Mm / 128, 3), 256>>>(x, wq, wk, wv);

    size_t smem = (size_t)4 * 64 * PAD * sizeof(float);   // 69,632 B
    cudaFuncSetAttribute(attn_kernel, cudaFuncAttributeMaxDynamicSharedMemorySize,
                         (int)smem);
    attn_kernel<<<dim3(Tt / 64, Bb), 256, smem>>>(out);
}